// round 9
// baseline (speedup 1.0000x reference)
#include <cuda_runtime.h>
#include <cuda_fp16.h>
#include <math.h>
#include <stdint.h>

// Problem constants
#define BQ   32
#define CINC 64
#define HH   32
#define WW   128
#define OCC  128
#define G5   640
#define KKK  320     // K = 128 (h_up) + 128 (h_lf) + 64 (x)
#define NDIR 4
#define NDIAG (HH + WW - 1)   // 159

#define MTILE 128    // 4 cells x 32 batch
#define NTILE 160    // 5 gates x 32 channels (permuted)
#define AKH   328    // padded K stride (halves)
#define CPAD  164    // padded C stride (floats)

#define A_SM   (MTILE * AKH * 2)          // 83,968
#define B_SM   (NTILE * AKH * 2)          // 104,960
#define BIAS_SM (NTILE * 4)               // 640
#define CSTATE_SM (2 * 128 * 32 * 4)      // 32,768 (double-buffered c cache)
#define SMEM_BYTES (A_SM + B_SM + BIAS_SM + CSTATE_SM)   // 222,336

// -------- device scratch --------
__device__ __half d_xT16[HH][WW][BQ][CINC];
__device__ __half d_BpT[NDIR][G5][KKK];
__device__ float  d_biasP[NDIR][G5];
__device__ __half d_h16[NDIR][HH][WW][BQ][OCC];
__device__ float  d_c32[NDIR][HH][WW][BQ][OCC];
__device__ int    d_bar[NDIR * 8 * 32];    // per-(dir,slot) counter, padded lines

// ---------------------------------------------------------------------------
// prep kernels
// ---------------------------------------------------------------------------
__global__ void prep_x(const float* __restrict__ x) {
    int i = blockIdx.x * blockDim.x + threadIdx.x;
    if (i >= HH * WW * BQ * CINC) return;
    int cin = i & 63;
    int b   = (i >> 6) & 31;
    int xw  = (i >> 11) & 127;
    int y   = i >> 18;
    ((__half*)d_xT16)[i] = __float2half(x[((b * CINC + cin) * HH + y) * WW + xw]);
}

__global__ void prep_w(const float* __restrict__ w0,
                       const float* __restrict__ u0,
                       const float* __restrict__ u1) {
    int i = blockIdx.x * blockDim.x + threadIdx.x;
    if (i >= NDIR * G5 * KKK) return;
    int k    = i % KKK;
    int pcol = (i / KKK) % G5;
    int d    = i / (G5 * KKK);
    int cbl  = pcol / NTILE;
    int rem  = pcol % NTILE;
    int gate = rem / 32;
    int lane = rem % 32;
    int gcol = gate * 128 + cbl * 32 + lane;
    float v;
    if (k < 128)        v = u0[(d * 128 + k) * G5 + gcol];
    else if (k < 256)   v = u1[(d * 128 + (k - 128)) * G5 + gcol];
    else                v = w0[(d * 64  + (k - 256)) * G5 + gcol];
    ((__half*)d_BpT)[i] = __float2half(v);
}

__global__ void prep_b(const float* __restrict__ bias) {
    int i = blockIdx.x * blockDim.x + threadIdx.x;
    if (i < NDIR * 8 * 32) d_bar[i] = 0;       // reset counters every replay
    if (i >= NDIR * G5) return;
    int pcol = i % G5;
    int d    = i / G5;
    int cbl  = pcol / NTILE;
    int rem  = pcol % NTILE;
    int gate = rem / 32;
    int lane = rem % 32;
    int gcol = gate * 128 + cbl * 32 + lane;
    d_biasP[d][pcol] = bias[d * G5 + gcol];
}

// ---------------------------------------------------------------------------
// fast device math / asm helpers
// ---------------------------------------------------------------------------
__device__ __forceinline__ float sig_f(float x) {
    return __fdividef(1.0f, 1.0f + __expf(-x));
}
__device__ __forceinline__ float tanh_f(float x) {
    float xc = fminf(fmaxf(x, -9.0f), 9.0f);
    float t  = __expf(2.0f * xc);
    return __fdividef(t - 1.0f, t + 1.0f);
}
__device__ __forceinline__ uint32_t smem_u32(const void* p) {
    return (uint32_t)__cvta_generic_to_shared(p);
}
__device__ __forceinline__ void ldsm_x4(uint32_t& r0, uint32_t& r1,
                                        uint32_t& r2, uint32_t& r3,
                                        uint32_t addr) {
    asm volatile("ldmatrix.sync.aligned.m8n8.x4.shared.b16 {%0,%1,%2,%3}, [%4];"
                 : "=r"(r0), "=r"(r1), "=r"(r2), "=r"(r3) : "r"(addr));
}
__device__ __forceinline__ void bar_add(int* p, int v) {
    asm volatile("red.release.gpu.add.s32 [%0], %1;" :: "l"(p), "r"(v) : "memory");
}
__device__ __forceinline__ int bar_ld(const int* p) {
    int v;
    asm volatile("ld.acquire.gpu.b32 %0, [%1];" : "=r"(v) : "l"(p) : "memory");
    return v;
}
// cp.async 16B, L2-only path (bypasses L1 -> coherent with peer st.cg),
// src_size 0 => zero-fill
__device__ __forceinline__ void cpasync_cg(uint32_t dst, const void* src, int sz) {
    asm volatile("cp.async.cg.shared.global [%0], [%1], 16, %2;"
                 :: "r"(dst), "l"(src), "r"(sz) : "memory");
}
__device__ __forceinline__ void cpasync_ca(uint32_t dst, const void* src, int sz) {
    asm volatile("cp.async.ca.shared.global [%0], [%1], 16, %2;"
                 :: "r"(dst), "l"(src), "r"(sz) : "memory");
}
__device__ __forceinline__ void cpasync_fence() {
    asm volatile("cp.async.commit_group;" ::: "memory");
    asm volatile("cp.async.wait_group 0;" ::: "memory");
}

// ---------------------------------------------------------------------------
// persistent wavefront kernel: 128 CTAs (4 dir x 4 cb x 8 slots), 1/SM.
// Slot m owns rows 4m..4m+3 for ALL diagonals; sync = neighbor flags only.
// ---------------------------------------------------------------------------
__global__ void __launch_bounds__(256, 1) persist_kernel() {
    const int bid   = blockIdx.x;
    const int d     = bid >> 5;
    const int cb    = (bid >> 3) & 3;
    const int slot  = bid & 7;
    const int tid   = threadIdx.x;

    extern __shared__ __align__(16) char smem_raw[];
    __half* As   = (__half*)smem_raw;                       // [128][AKH]
    __half* Bs   = As + MTILE * AKH;                        // [160][AKH]
    float*  bsm  = (float*)((char*)smem_raw + A_SM + B_SM); // [160]
    float*  csm  = bsm + NTILE;                             // [2][128][32]
    float*  Csm  = (float*)smem_raw;                        // [128][CPAD], overlaps As

    // ---- stage B slice + bias ONCE ----
    for (int c = tid; c < NTILE * 40; c += 256) {
        int n = c / 40;
        int q = c - n * 40;
        *(uint4*)&Bs[n * AKH + q * 8] =
            *(const uint4*)&d_BpT[d][cb * NTILE + n][q * 8];
    }
    for (int i = tid; i < NTILE; i += 256) bsm[i] = d_biasP[d][cb * NTILE + i];
    __syncthreads();

    int* barS = &d_bar[(d * 8 + slot) * 32];
    int* barP = barS - 32;

    // credit for skipped leading diagonals (t < 4*slot)
    if (tid == 0 && slot > 0) bar_add(barS, 4 * slot);

    const int warp  = tid >> 5;
    const int lane  = tid & 31;
    const int wm    = warp & 3;
    const int wh    = warp >> 2;   // pair half (also wn for MMA)
    const int g     = lane >> 2;
    const int tq    = lane & 3;
    const int lane7 = lane & 7;
    const int lb8   = (lane >> 3) & 1;
    const int lb16  = lane >> 4;

    // bias registers (channel = lane, fixed)
    const float bI = bsm[lane];
    const float bF = bsm[32 + lane];
    const float bG = bsm[64 + lane];
    const float bO = bsm[96 + lane];
    const float bL = bsm[128 + lane];

    const uint32_t aAddr0 =
        smem_u32(&As[(wm * 32 + lane7 + lb8 * 8) * AKH + lb16 * 8]);
    const uint32_t aAddr1 = aAddr0 + 16 * AKH * 2;
    uint32_t bAddr[5];
#pragma unroll
    for (int n2 = 0; n2 < 5; n2++)
        bAddr[n2] = smem_u32(
            &Bs[(wh * 80 + n2 * 16 + lb16 * 8 + lane7) * AKH + lb8 * 8]);

    // A-stage phase-A constants
    const int clA   = warp >> 1;
    const int bA0   = (warp & 1) * 16;
    const int selLf = (lane >= 16);
    const int koffA = (lane * 8) & 127;
    const int yA    = slot * 4 + clA;      // absolute row for phase A, constant

    // epilogue constants (pair-ownership rows)
    const int yE = slot * 4 + wm;          // epilogue row y, constant per warp
    const uint32_t asBase = smem_u32(As);

    const int t0 = 4 * slot;
    const int t1 = (4 * slot + 130 < NDIAG - 1) ? (4 * slot + 130) : (NDIAG - 1);

    for (int t = t0; t <= t1; t++) {
        // ===== phase B (static x for diag t) — issued before flag wait =====
        {
            int b  = tid >> 3;
            int q8 = tid & 7;
#pragma unroll
            for (int i = 0; i < 4; i++) {
                int y  = slot * 4 + i;
                int x  = t - y;
                bool ok = (x >= 0 && x < WW);
                int fy = (d & 2) ? (HH - 1 - y) : y;
                int fx = (d & 1) ? (WW - 1 - x) : x;
                int fyc = ok ? fy : 0, fxc = ok ? fx : 0;
                uint32_t dst = asBase + ((i * 32 + b) * AKH + 256 + q8 * 8) * 2;
                cpasync_ca(dst, &d_xT16[fyc][fxc][b][q8 * 8], ok ? 16 : 0);
            }
        }

        // ---- wait: own slot cb-peers + slot-1 done through diag t-1 ----
        if (tid == 0) {
            const int tgt = 4 * t;
            while (bar_ld(barS) < tgt) { }
            if (slot > 0) while (bar_ld(barP) < tgt) { }
        }
        __syncthreads();

        // ===== phase A: recurrent K (h_up | h_lf), cp.async.cg =====
        {
            int x     = t - yA;
            bool valid = (x >= 0) && (x < WW);
            bool up_ok = valid && (yA > 0);
            bool lf_ok = valid && (x > 0);
            int yu = up_ok ? yA - 1 : 0;
            int xl = lf_ok ? x - 1 : 0;
            int xc = valid ? x : 0;
            const __half* pUp = &d_h16[d][yu][xc][0][0];
            const __half* pLf = &d_h16[d][yA][xl][0][0];
            const __half* pSel = selLf ? pLf : pUp;
            const int sz = (selLf ? lf_ok : up_ok) ? 16 : 0;
#pragma unroll
            for (int i = 0; i < 16; i++) {
                int r = warp * 16 + i;
                uint32_t dst = asBase + (r * AKH + lane * 8) * 2;
                cpasync_cg(dst, pSel + (bA0 + i) * 128 + koffA, sz);
            }
        }
        cpasync_fence();
        __syncthreads();

        // ===== MMA mainloop =====
        float acc[2][10][4];
#pragma unroll
        for (int mi = 0; mi < 2; mi++)
#pragma unroll
            for (int ni = 0; ni < 10; ni++)
#pragma unroll
                for (int e = 0; e < 4; e++) acc[mi][ni][e] = 0.0f;

#pragma unroll 5
        for (int ks = 0; ks < 20; ks++) {
            const uint32_t kb = ks * 32;
            uint32_t a0[4], a1[4];
            ldsm_x4(a0[0], a0[1], a0[2], a0[3], aAddr0 + kb);
            ldsm_x4(a1[0], a1[1], a1[2], a1[3], aAddr1 + kb);
#pragma unroll
            for (int n2 = 0; n2 < 5; n2++) {
                uint32_t b0, b1, b2, b3;
                ldsm_x4(b0, b1, b2, b3, bAddr[n2] + kb);
#pragma unroll
                for (int mi = 0; mi < 2; mi++) {
                    uint32_t* af = mi ? a1 : a0;
                    asm volatile(
                        "mma.sync.aligned.m16n8k16.row.col.f32.f16.f16.f32 "
                        "{%0,%1,%2,%3}, {%4,%5,%6,%7}, {%8,%9}, {%0,%1,%2,%3};\n"
                        : "+f"(acc[mi][2*n2][0]), "+f"(acc[mi][2*n2][1]),
                          "+f"(acc[mi][2*n2][2]), "+f"(acc[mi][2*n2][3])
                        : "r"(af[0]), "r"(af[1]), "r"(af[2]), "r"(af[3]),
                          "r"(b0), "r"(b1));
                    asm volatile(
                        "mma.sync.aligned.m16n8k16.row.col.f32.f16.f16.f32 "
                        "{%0,%1,%2,%3}, {%4,%5,%6,%7}, {%8,%9}, {%0,%1,%2,%3};\n"
                        : "+f"(acc[mi][2*n2+1][0]), "+f"(acc[mi][2*n2+1][1]),
                          "+f"(acc[mi][2*n2+1][2]), "+f"(acc[mi][2*n2+1][3])
                        : "r"(af[0]), "r"(af[1]), "r"(af[2]), "r"(af[3]),
                          "r"(b2), "r"(b3));
                }
            }
        }
        // pair barrier: rows wm*32..+31 of As read only by warps wm, wm+4
        asm volatile("bar.sync %0, 64;" :: "r"(1 + wm) : "memory");

        // ===== spill gates to smem (pair-local rows) =====
#pragma unroll
        for (int mi = 0; mi < 2; mi++) {
#pragma unroll
            for (int ni = 0; ni < 10; ni++) {
                int row = wm * 32 + mi * 16 + g;
                int col = wh * 80 + ni * 8 + tq * 2;
                *(float2*)&Csm[row * CPAD + col] =
                    make_float2(acc[mi][ni][0], acc[mi][ni][1]);
                *(float2*)&Csm[(row + 8) * CPAD + col] =
                    make_float2(acc[mi][ni][2], acc[mi][ni][3]);
            }
        }
        asm volatile("bar.sync %0, 64;" :: "r"(1 + wm) : "memory");

        // ===== LSTM epilogue: rows r = wm*32 + 2i + wh (pair ownership) =====
        {
            const int x = t - yE;
            const bool cellok = (x >= 0 && x < WW);
            const float* csmPR = csm + ((t & 1) ^ 1) * (128 * 32);
            float*       csmPW = csm + (t & 1) * (128 * 32);
            if (cellok) {
                const int j = lane;
                const int oc = cb * 32 + j;
#pragma unroll
                for (int i = 0; i < 16; i++) {
                    int b = i * 2 + wh;
                    int r = wm * 32 + b;
                    const float* cr = &Csm[r * CPAD];
                    float gi = cr[j]       + bI;
                    float gf = cr[32 + j]  + bF;
                    float gg = cr[64 + j]  + bG;
                    float go = cr[96 + j]  + bO;
                    float gl = cr[128 + j] + bL;
                    float iv = sig_f(gi);
                    float fv = sig_f(gf);
                    float gv = tanh_f(gg);
                    float ov = sig_f(go);
                    float lv = sig_f(gl);
                    float clf = (x > 0) ? csmPR[r * 32 + j] : 0.0f;
                    float cup;
                    if (wm > 0)       cup = csmPR[(r - 32) * 32 + j];
                    else if (yE > 0)  cup = __ldcg(&d_c32[d][yE - 1][x][b][oc]);
                    else              cup = 0.0f;
                    float cn = fv * (lv * cup + (1.0f - lv) * clf) + iv * gv;
                    float hn = ov * tanh_f(cn);
                    csmPW[r * 32 + j] = cn;
                    if (wm == 3) __stcg(&d_c32[d][yE][x][b][oc], cn);
                    unsigned short hraw = __half_as_ushort(__float2half(hn));
                    asm volatile("st.global.cg.u16 [%0], %1;"
                                 :: "l"(&d_h16[d][yE][x][b][oc]), "h"(hraw)
                                 : "memory");
                }
            }
        }
        __syncthreads();   // all threads' stores issued before release

        if (tid == 0) bar_add(barS, 1);
    }

    // credit for skipped trailing diagonals
    if (tid == 0) {
        int tail = (NDIAG - 1) - t1;
        if (tail > 0) bar_add(barS, tail);
    }
}

// ---------------------------------------------------------------------------
// final transpose: h16[d][y][xw][b][oc] -> out[b][d][oc][y][xw]
// ---------------------------------------------------------------------------
__global__ void __launch_bounds__(256) finalize_kernel(float* __restrict__ out) {
    int bid = blockIdx.x;
    int occ = bid & 3;
    int b   = (bid >> 2) & 31;
    int y   = (bid >> 7) & 31;
    int d   = bid >> 12;

    __shared__ float sm[128][33];

    for (int i = threadIdx.x; i < 128 * 32; i += 256) {
        int xw = i >> 5;
        int j  = i & 31;
        sm[xw][j] = __half2float(d_h16[d][y][xw][b][occ * 32 + j]);
    }
    __syncthreads();
    for (int i = threadIdx.x; i < 32 * 128; i += 256) {
        int j  = i >> 7;
        int xw = i & 127;
        int oc = occ * 32 + j;
        out[(((size_t)(b * 4 + d) * OCC + oc) * HH + y) * WW + xw] = sm[xw][j];
    }
}

// ---------------------------------------------------------------------------
// launch
// ---------------------------------------------------------------------------
extern "C" void kernel_launch(void* const* d_in, const int* in_sizes, int n_in,
                              void* d_out, int out_size) {
    const float* x  = (const float*)d_in[0];
    const float* w0 = (const float*)d_in[1];
    const float* u0 = (const float*)d_in[2];
    const float* u1 = (const float*)d_in[3];
    const float* bb = (const float*)d_in[4];
    float* out = (float*)d_out;
    (void)in_sizes; (void)n_in; (void)out_size;

    cudaFuncSetAttribute(persist_kernel,
                         cudaFuncAttributeMaxDynamicSharedMemorySize, SMEM_BYTES);

    prep_x<<<(HH * WW * BQ * CINC + 255) / 256, 256>>>(x);
    prep_w<<<(NDIR * G5 * KKK + 255) / 256, 256>>>(w0, u0, u1);
    prep_b<<<(NDIR * G5 + 255) / 256, 256>>>(bb);

    persist_kernel<<<128, 256, SMEM_BYTES>>>();

    finalize_kernel<<<NDIR * HH * BQ * 4, 256>>>(out);
}

// round 10
// speedup vs baseline: 1.2213x; 1.2213x over previous
#include <cuda_runtime.h>
#include <cuda_fp16.h>
#include <math.h>
#include <stdint.h>

// Problem constants
#define BQ   32
#define CINC 64
#define HH   32
#define WW   128
#define OCC  128
#define G5   640
#define KKK  320     // K = 128 (h_up) + 128 (h_lf) + 64 (x)
#define NDIR 4
#define NDIAG (HH + WW - 1)   // 159

#define MTILE 128    // 4 cells x 32 batch
#define NTILE 160    // 5 gates x 32 channels (permuted)
#define AKH   328    // padded K stride (halves)
#define CPAD  164    // padded C stride (floats)

#define A_SM   (MTILE * AKH * 2)          // 83,968
#define B_SM   (NTILE * AKH * 2)          // 104,960
#define BIAS_SM (NTILE * 4)               // 640
#define CSTATE_SM (2 * 128 * 32 * 4)      // 32,768 (double-buffered c cache)
#define SMEM_BYTES (A_SM + B_SM + BIAS_SM + CSTATE_SM)   // 222,336

// -------- device scratch --------
__device__ __half d_xT16[HH][WW][BQ][CINC];
__device__ __half d_BpT[NDIR][G5][KKK];
__device__ float  d_biasP[NDIR][G5];
__device__ __half d_h16[NDIR][HH][WW][BQ][OCC];
__device__ float  d_c32[NDIR][HH][WW][BQ][OCC];
__device__ int    d_bar[NDIR * 8 * 32];    // per-(dir,slot) counter, padded lines

// ---------------------------------------------------------------------------
// prep kernels
// ---------------------------------------------------------------------------
__global__ void prep_x(const float* __restrict__ x) {
    int i = blockIdx.x * blockDim.x + threadIdx.x;
    if (i >= HH * WW * BQ * CINC) return;
    int cin = i & 63;
    int b   = (i >> 6) & 31;
    int xw  = (i >> 11) & 127;
    int y   = i >> 18;
    ((__half*)d_xT16)[i] = __float2half(x[((b * CINC + cin) * HH + y) * WW + xw]);
}

__global__ void prep_w(const float* __restrict__ w0,
                       const float* __restrict__ u0,
                       const float* __restrict__ u1) {
    int i = blockIdx.x * blockDim.x + threadIdx.x;
    if (i >= NDIR * G5 * KKK) return;
    int k    = i % KKK;
    int pcol = (i / KKK) % G5;
    int d    = i / (G5 * KKK);
    int cbl  = pcol / NTILE;
    int rem  = pcol % NTILE;
    int gate = rem / 32;
    int lane = rem % 32;
    int gcol = gate * 128 + cbl * 32 + lane;
    float v;
    if (k < 128)        v = u0[(d * 128 + k) * G5 + gcol];
    else if (k < 256)   v = u1[(d * 128 + (k - 128)) * G5 + gcol];
    else                v = w0[(d * 64  + (k - 256)) * G5 + gcol];
    ((__half*)d_BpT)[i] = __float2half(v);
}

__global__ void prep_b(const float* __restrict__ bias) {
    int i = blockIdx.x * blockDim.x + threadIdx.x;
    if (i < NDIR * 8 * 32) d_bar[i] = 0;       // reset counters every replay
    if (i >= NDIR * G5) return;
    int pcol = i % G5;
    int d    = i / G5;
    int cbl  = pcol / NTILE;
    int rem  = pcol % NTILE;
    int gate = rem / 32;
    int lane = rem % 32;
    int gcol = gate * 128 + cbl * 32 + lane;
    d_biasP[d][pcol] = bias[d * G5 + gcol];
}

// ---------------------------------------------------------------------------
// fast device math / asm helpers
// ---------------------------------------------------------------------------
__device__ __forceinline__ float sig_f(float x) {
    return __fdividef(1.0f, 1.0f + __expf(-x));
}
__device__ __forceinline__ float tanh_f(float x) {
    float xc = fminf(fmaxf(x, -9.0f), 9.0f);
    float t  = __expf(2.0f * xc);
    return __fdividef(t - 1.0f, t + 1.0f);
}
__device__ __forceinline__ uint32_t smem_u32(const void* p) {
    return (uint32_t)__cvta_generic_to_shared(p);
}
__device__ __forceinline__ void ldsm_x4(uint32_t& r0, uint32_t& r1,
                                        uint32_t& r2, uint32_t& r3,
                                        uint32_t addr) {
    asm volatile("ldmatrix.sync.aligned.m8n8.x4.shared.b16 {%0,%1,%2,%3}, [%4];"
                 : "=r"(r0), "=r"(r1), "=r"(r2), "=r"(r3) : "r"(addr));
}
__device__ __forceinline__ void bar_add(int* p, int v) {
    asm volatile("red.release.gpu.add.s32 [%0], %1;" :: "l"(p), "r"(v) : "memory");
}
__device__ __forceinline__ int bar_ld(const int* p) {
    int v;
    asm volatile("ld.acquire.gpu.b32 %0, [%1];" : "=r"(v) : "l"(p) : "memory");
    return v;
}
#define MMA_16816(ACC, A0, A1, A2, A3, B0, B1)                                 \
    asm volatile(                                                              \
        "mma.sync.aligned.m16n8k16.row.col.f32.f16.f16.f32 "                   \
        "{%0,%1,%2,%3}, {%4,%5,%6,%7}, {%8,%9}, {%0,%1,%2,%3};\n"              \
        : "+f"((ACC)[0]), "+f"((ACC)[1]), "+f"((ACC)[2]), "+f"((ACC)[3])       \
        : "r"(A0), "r"(A1), "r"(A2), "r"(A3), "r"(B0), "r"(B1))

// ---------------------------------------------------------------------------
// persistent wavefront kernel: 128 CTAs (4 dir x 4 cb x 8 slots), 1/SM.
// Slot m owns rows 4m..4m+3 for ALL diagonals; sync = neighbor flags only.
// ---------------------------------------------------------------------------
__global__ void __launch_bounds__(256, 1) persist_kernel() {
    const int bid   = blockIdx.x;
    const int d     = bid >> 5;
    const int cb    = (bid >> 3) & 3;
    const int slot  = bid & 7;
    const int tid   = threadIdx.x;

    extern __shared__ __align__(16) char smem_raw[];
    __half* As   = (__half*)smem_raw;                       // [128][AKH]
    __half* Bs   = As + MTILE * AKH;                        // [160][AKH]
    float*  bsm  = (float*)((char*)smem_raw + A_SM + B_SM); // [160]
    float*  csm  = bsm + NTILE;                             // [2][128][32]
    float*  Csm  = (float*)smem_raw;                        // [128][CPAD], overlaps As

    // ---- stage B slice + bias ONCE ----
    for (int c = tid; c < NTILE * 40; c += 256) {
        int n = c / 40;
        int q = c - n * 40;
        *(uint4*)&Bs[n * AKH + q * 8] =
            *(const uint4*)&d_BpT[d][cb * NTILE + n][q * 8];
    }
    for (int i = tid; i < NTILE; i += 256) bsm[i] = d_biasP[d][cb * NTILE + i];
    __syncthreads();

    int* barS = &d_bar[(d * 8 + slot) * 32];
    int* barP = barS - 32;

    // credit for skipped leading diagonals (t < 4*slot)
    if (tid == 0 && slot > 0) bar_add(barS, 4 * slot);

    const int warp  = tid >> 5;
    const int lane  = tid & 31;
    const int wm    = warp & 3;
    const int wn    = warp >> 2;
    const int g     = lane >> 2;
    const int tq    = lane & 3;
    const int lane7 = lane & 7;
    const int lb8   = (lane >> 3) & 1;
    const int lb16  = lane >> 4;

    // bias registers (channel = lane, fixed over whole t-loop)
    const float bI = bsm[lane];
    const float bF = bsm[32 + lane];
    const float bG = bsm[64 + lane];
    const float bO = bsm[96 + lane];
    const float bL = bsm[128 + lane];

    const uint32_t aAddr0 =
        smem_u32(&As[(wm * 32 + lane7 + lb8 * 8) * AKH + lb16 * 8]);
    const uint32_t aAddr1 = aAddr0 + 16 * AKH * 2;
    uint32_t bAddr[5];
#pragma unroll
    for (int n2 = 0; n2 < 5; n2++)
        bAddr[n2] = smem_u32(
            &Bs[(wn * 80 + n2 * 16 + lb16 * 8 + lane7) * AKH + lb8 * 8]);

    // A-stage phase-A constants
    const int clA   = warp >> 1;
    const int bA0   = (warp & 1) * 16;
    const int selLf = (lane >= 16);
    const int koffA = (lane * 8) & 127;
    const int yA    = slot * 4 + clA;      // absolute row, constant

    const int t0 = 4 * slot;
    const int t1 = (4 * slot + 130 < NDIAG - 1) ? (4 * slot + 130) : (NDIAG - 1);

    for (int t = t0; t <= t1; t++) {
        // ---- wait: own slot peers + slot-1 done through diag t-1 ----
        if (tid == 0) {
            const int tgt = 4 * t;
            while (bar_ld(barS) < tgt) { }
            if (slot > 0) while (bar_ld(barP) < tgt) { }
        }
        __syncthreads();

        // ===== A-stage phase A: recurrent K (h_up | h_lf) =====
        {
            int x     = t - yA;
            bool valid = (x >= 0) && (x < WW);
            bool up_ok = valid && (yA > 0);
            bool lf_ok = valid && (x > 0);
            int yu = up_ok ? yA - 1 : 0;
            int xl = lf_ok ? x - 1 : 0;
            int xc = valid ? x : 0;
            const __half* pUp = &d_h16[d][yu][xc][0][0];
            const __half* pLf = &d_h16[d][yA][xl][0][0];
            const __half* pSel = selLf ? pLf : pUp;
            const bool pok = selLf ? lf_ok : up_ok;
#pragma unroll
            for (int i = 0; i < 16; i++) {
                int r = warp * 16 + i;
                uint4 v = make_uint4(0u, 0u, 0u, 0u);
                if (pok) v = __ldcg((const uint4*)(pSel + (bA0 + i) * 128 + koffA));
                *(uint4*)&As[r * AKH + lane * 8] = v;
            }
        }
        // ===== A-stage phase B: x slice (K 256..319) =====
        {
            int b  = tid >> 3;
            int q8 = tid & 7;
#pragma unroll
            for (int i = 0; i < 4; i++) {
                int y  = slot * 4 + i;
                int x  = t - y;
                uint4 v = make_uint4(0u, 0u, 0u, 0u);
                if (x >= 0 && x < WW) {
                    int fy = (d & 2) ? (HH - 1 - y) : y;
                    int fx = (d & 1) ? (WW - 1 - x) : x;
                    v = __ldcg((const uint4*)&d_xT16[fy][fx][b][q8 * 8]);
                }
                *(uint4*)&As[(i * 32 + b) * AKH + 256 + q8 * 8] = v;
            }
        }
        __syncthreads();

        // ===== MMA mainloop: software-pipelined (double-buffered frags) =====
        float acc[2][10][4];
#pragma unroll
        for (int mi = 0; mi < 2; mi++)
#pragma unroll
            for (int ni = 0; ni < 10; ni++)
#pragma unroll
                for (int e = 0; e < 4; e++) acc[mi][ni][e] = 0.0f;

        uint32_t afA[2][4], afB[2][4], bfr[2][20];
        // prologue: frags for k-step 0
        ldsm_x4(afA[0][0], afA[0][1], afA[0][2], afA[0][3], aAddr0);
        ldsm_x4(afB[0][0], afB[0][1], afB[0][2], afB[0][3], aAddr1);
#pragma unroll
        for (int n2 = 0; n2 < 5; n2++)
            ldsm_x4(bfr[0][n2*4], bfr[0][n2*4+1], bfr[0][n2*4+2], bfr[0][n2*4+3],
                    bAddr[n2]);

#pragma unroll
        for (int ks = 0; ks < 20; ks++) {
            const int cur = ks & 1;
            const int nxt = cur ^ 1;
            if (ks < 19) {   // prefetch next k-step while MMAs of cur issue
                const uint32_t kb = (ks + 1) * 32;
                ldsm_x4(afA[nxt][0], afA[nxt][1], afA[nxt][2], afA[nxt][3],
                        aAddr0 + kb);
                ldsm_x4(afB[nxt][0], afB[nxt][1], afB[nxt][2], afB[nxt][3],
                        aAddr1 + kb);
#pragma unroll
                for (int n2 = 0; n2 < 5; n2++)
                    ldsm_x4(bfr[nxt][n2*4], bfr[nxt][n2*4+1],
                            bfr[nxt][n2*4+2], bfr[nxt][n2*4+3],
                            bAddr[n2] + kb);
            }
#pragma unroll
            for (int n2 = 0; n2 < 5; n2++) {
                MMA_16816(acc[0][2*n2],   afA[cur][0], afA[cur][1], afA[cur][2],
                          afA[cur][3], bfr[cur][n2*4],   bfr[cur][n2*4+1]);
                MMA_16816(acc[0][2*n2+1], afA[cur][0], afA[cur][1], afA[cur][2],
                          afA[cur][3], bfr[cur][n2*4+2], bfr[cur][n2*4+3]);
                MMA_16816(acc[1][2*n2],   afB[cur][0], afB[cur][1], afB[cur][2],
                          afB[cur][3], bfr[cur][n2*4],   bfr[cur][n2*4+1]);
                MMA_16816(acc[1][2*n2+1], afB[cur][0], afB[cur][1], afB[cur][2],
                          afB[cur][3], bfr[cur][n2*4+2], bfr[cur][n2*4+3]);
            }
        }
        __syncthreads();   // done reading As before overwriting with Csm

        // ===== spill gates to smem =====
#pragma unroll
        for (int mi = 0; mi < 2; mi++) {
#pragma unroll
            for (int ni = 0; ni < 10; ni++) {
                int row = wm * 32 + mi * 16 + g;
                int col = wn * 80 + ni * 8 + tq * 2;
                *(float2*)&Csm[row * CPAD + col] =
                    make_float2(acc[mi][ni][0], acc[mi][ni][1]);
                *(float2*)&Csm[(row + 8) * CPAD + col] =
                    make_float2(acc[mi][ni][2], acc[mi][ni][3]);
            }
        }
        __syncthreads();

        // ===== LSTM epilogue: c-state from smem ring =====
        const float* csmPR = csm + ((t & 1) ^ 1) * (128 * 32);
        float*       csmPW = csm + (t & 1) * (128 * 32);
#pragma unroll
        for (int i = 0; i < 16; i++) {
            int r  = i * 8 + warp;
            int j  = lane;
            int cl = r >> 5, b = r & 31;
            int y  = slot * 4 + cl;
            int x  = t - y;
            if (x >= 0 && x < WW) {
                const float* cr = &Csm[r * CPAD];
                float gi = cr[j]       + bI;
                float gf = cr[32 + j]  + bF;
                float gg = cr[64 + j]  + bG;
                float go = cr[96 + j]  + bO;
                float gl = cr[128 + j] + bL;
                float iv = sig_f(gi);
                float fv = sig_f(gf);
                float gv = tanh_f(gg);
                float ov = sig_f(go);
                float lv = sig_f(gl);
                int oc = cb * 32 + j;
                float clf = (x > 0) ? csmPR[r * 32 + j] : 0.0f;
                float cup;
                if (cl > 0)       cup = csmPR[(r - 32) * 32 + j];
                else if (y > 0)   cup = __ldcg(&d_c32[d][y - 1][x][b][oc]);
                else              cup = 0.0f;
                float cn = fv * (lv * cup + (1.0f - lv) * clf) + iv * gv;
                float hn = ov * tanh_f(cn);
                csmPW[r * 32 + j] = cn;
                if (cl == 3) __stcg(&d_c32[d][y][x][b][oc], cn);   // boundary publish
                unsigned short hraw = __half_as_ushort(__float2half(hn));
                asm volatile("st.global.cg.u16 [%0], %1;"
                             :: "l"(&d_h16[d][y][x][b][oc]), "h"(hraw) : "memory");
            }
        }
        __syncthreads();   // all threads' stores issued before release

        if (tid == 0) bar_add(barS, 1);
    }

    // credit for skipped trailing diagonals
    if (tid == 0) {
        int tail = (NDIAG - 1) - t1;
        if (tail > 0) bar_add(barS, tail);
    }
}

// ---------------------------------------------------------------------------
// final transpose: h16[d][y][xw][b][oc] -> out[b][d][oc][y][xw]
// ---------------------------------------------------------------------------
__global__ void __launch_bounds__(256) finalize_kernel(float* __restrict__ out) {
    int bid = blockIdx.x;
    int occ = bid & 3;
    int b   = (bid >> 2) & 31;
    int y   = (bid >> 7) & 31;
    int d   = bid >> 12;

    __shared__ float sm[128][33];

    for (int i = threadIdx.x; i < 128 * 32; i += 256) {
        int xw = i >> 5;
        int j  = i & 31;
        sm[xw][j] = __half2float(d_h16[d][y][xw][b][occ * 32 + j]);
    }
    __syncthreads();
    for (int i = threadIdx.x; i < 32 * 128; i += 256) {
        int j  = i >> 7;
        int xw = i & 127;
        int oc = occ * 32 + j;
        out[(((size_t)(b * 4 + d) * OCC + oc) * HH + y) * WW + xw] = sm[xw][j];
    }
}

// ---------------------------------------------------------------------------
// launch
// ---------------------------------------------------------------------------
extern "C" void kernel_launch(void* const* d_in, const int* in_sizes, int n_in,
                              void* d_out, int out_size) {
    const float* x  = (const float*)d_in[0];
    const float* w0 = (const float*)d_in[1];
    const float* u0 = (const float*)d_in[2];
    const float* u1 = (const float*)d_in[3];
    const float* bb = (const float*)d_in[4];
    float* out = (float*)d_out;
    (void)in_sizes; (void)n_in; (void)out_size;

    cudaFuncSetAttribute(persist_kernel,
                         cudaFuncAttributeMaxDynamicSharedMemorySize, SMEM_BYTES);

    prep_x<<<(HH * WW * BQ * CINC + 255) / 256, 256>>>(x);
    prep_w<<<(NDIR * G5 * KKK + 255) / 256, 256>>>(w0, u0, u1);
    prep_b<<<(NDIR * G5 + 255) / 256, 256>>>(bb);

    persist_kernel<<<128, 256, SMEM_BYTES>>>();

    finalize_kernel<<<NDIR * HH * BQ * 4, 256>>>(out);
}

// round 11
// speedup vs baseline: 1.2993x; 1.0639x over previous
#include <cuda_runtime.h>
#include <cuda_fp16.h>
#include <math.h>
#include <stdint.h>

// Problem constants
#define BQ   32
#define CINC 64
#define HH   32
#define WW   128
#define OCC  128
#define G5   640
#define KKK  320     // K = 128 (h_up) + 128 (h_lf) + 64 (x)
#define NDIR 4
#define NDIAG (HH + WW - 1)   // 159

#define MTILE 128    // 4 cells x 32 batch
#define NTILE 160    // 5 gates x 32 channels (permuted)
#define AKH   328    // padded K stride (halves)
#define CPAD  164    // padded C stride (floats)

#define A_SM   (MTILE * AKH * 2)          // 83,968
#define B_SM   (NTILE * AKH * 2)          // 104,960
#define BIAS_SM (NTILE * 4)               // 640
#define CSTATE_SM (2 * 128 * 32 * 4)      // 32,768 (double-buffered c cache)
#define SMEM_BYTES (A_SM + B_SM + BIAS_SM + CSTATE_SM)   // 222,336

// -------- device scratch --------
__device__ __half d_xT16[HH][WW][BQ][CINC];
__device__ __half d_BpT[NDIR][G5][KKK];
__device__ float  d_biasP[NDIR][G5];
__device__ __half d_h16[NDIR][HH][WW][BQ][OCC];
__device__ float  d_c32[NDIR][HH][WW][BQ][OCC];
__device__ int    d_bar[NDIR * 8 * 32];    // per-(dir,slot) counter, padded lines

// ---------------------------------------------------------------------------
// prep kernels
// ---------------------------------------------------------------------------
__global__ void prep_x(const float* __restrict__ x) {
    int i = blockIdx.x * blockDim.x + threadIdx.x;
    if (i >= HH * WW * BQ * CINC) return;
    int cin = i & 63;
    int b   = (i >> 6) & 31;
    int xw  = (i >> 11) & 127;
    int y   = i >> 18;
    ((__half*)d_xT16)[i] = __float2half(x[((b * CINC + cin) * HH + y) * WW + xw]);
}

__global__ void prep_w(const float* __restrict__ w0,
                       const float* __restrict__ u0,
                       const float* __restrict__ u1) {
    int i = blockIdx.x * blockDim.x + threadIdx.x;
    if (i >= NDIR * G5 * KKK) return;
    int k    = i % KKK;
    int pcol = (i / KKK) % G5;
    int d    = i / (G5 * KKK);
    int cbl  = pcol / NTILE;
    int rem  = pcol % NTILE;
    int gate = rem / 32;
    int lane = rem % 32;
    int gcol = gate * 128 + cbl * 32 + lane;
    float v;
    if (k < 128)        v = u0[(d * 128 + k) * G5 + gcol];
    else if (k < 256)   v = u1[(d * 128 + (k - 128)) * G5 + gcol];
    else                v = w0[(d * 64  + (k - 256)) * G5 + gcol];
    ((__half*)d_BpT)[i] = __float2half(v);
}

__global__ void prep_b(const float* __restrict__ bias) {
    int i = blockIdx.x * blockDim.x + threadIdx.x;
    if (i < NDIR * 8 * 32) d_bar[i] = 0;       // reset counters every replay
    if (i >= NDIR * G5) return;
    int pcol = i % G5;
    int d    = i / G5;
    int cbl  = pcol / NTILE;
    int rem  = pcol % NTILE;
    int gate = rem / 32;
    int lane = rem % 32;
    int gcol = gate * 128 + cbl * 32 + lane;
    d_biasP[d][pcol] = bias[d * G5 + gcol];
}

// ---------------------------------------------------------------------------
// fast device math / asm helpers
// ---------------------------------------------------------------------------
__device__ __forceinline__ float sig_f(float x) {        // exact-ish (2 MUFU)
    return __fdividef(1.0f, 1.0f + __expf(-x));
}
__device__ __forceinline__ float tanh_a(float x) {       // 1 MUFU
    float t;
    asm("tanh.approx.f32 %0, %1;" : "=f"(t) : "f"(x));
    return t;
}
__device__ __forceinline__ float sig_a(float x) {        // 1 MUFU + 2 FMA
    float t;
    asm("tanh.approx.f32 %0, %1;" : "=f"(t) : "f"(0.5f * x));
    return fmaf(0.5f, t, 0.5f);
}
__device__ __forceinline__ uint32_t smem_u32(const void* p) {
    return (uint32_t)__cvta_generic_to_shared(p);
}
__device__ __forceinline__ void ldsm_x4(uint32_t& r0, uint32_t& r1,
                                        uint32_t& r2, uint32_t& r3,
                                        uint32_t addr) {
    asm volatile("ldmatrix.sync.aligned.m8n8.x4.shared.b16 {%0,%1,%2,%3}, [%4];"
                 : "=r"(r0), "=r"(r1), "=r"(r2), "=r"(r3) : "r"(addr));
}
__device__ __forceinline__ void bar_add(int* p, int v) {
    asm volatile("red.release.gpu.add.s32 [%0], %1;" :: "l"(p), "r"(v) : "memory");
}
__device__ __forceinline__ int bar_ld(const int* p) {
    int v;
    asm volatile("ld.acquire.gpu.b32 %0, [%1];" : "=r"(v) : "l"(p) : "memory");
    return v;
}
#define MMA_16816(ACC, A0, A1, A2, A3, B0, B1)                                 \
    asm volatile(                                                              \
        "mma.sync.aligned.m16n8k16.row.col.f32.f16.f16.f32 "                   \
        "{%0,%1,%2,%3}, {%4,%5,%6,%7}, {%8,%9}, {%0,%1,%2,%3};\n"              \
        : "+f"((ACC)[0]), "+f"((ACC)[1]), "+f"((ACC)[2]), "+f"((ACC)[3])       \
        : "r"(A0), "r"(A1), "r"(A2), "r"(A3), "r"(B0), "r"(B1))

// ---------------------------------------------------------------------------
// persistent wavefront kernel: 128 CTAs (4 dir x 4 cb x 8 slots), 1/SM.
// Slot m owns rows 4m..4m+3 for ALL diagonals; sync = neighbor flags only.
// Flag units: 8 per CTA per diag (one per warp), 32/diag across 4 cb CTAs.
// ---------------------------------------------------------------------------
__global__ void __launch_bounds__(256, 1) persist_kernel() {
    const int bid   = blockIdx.x;
    const int d     = bid >> 5;
    const int cb    = (bid >> 3) & 3;
    const int slot  = bid & 7;
    const int tid   = threadIdx.x;

    extern __shared__ __align__(16) char smem_raw[];
    __half* As   = (__half*)smem_raw;                       // [128][AKH]
    __half* Bs   = As + MTILE * AKH;                        // [160][AKH]
    float*  bsm  = (float*)((char*)smem_raw + A_SM + B_SM); // [160]
    float*  csm  = bsm + NTILE;                             // [2][128][32]
    float*  Csm  = (float*)smem_raw;                        // [128][CPAD], overlaps As

    // ---- stage B slice + bias ONCE ----
    for (int c = tid; c < NTILE * 40; c += 256) {
        int n = c / 40;
        int q = c - n * 40;
        *(uint4*)&Bs[n * AKH + q * 8] =
            *(const uint4*)&d_BpT[d][cb * NTILE + n][q * 8];
    }
    for (int i = tid; i < NTILE; i += 256) bsm[i] = d_biasP[d][cb * NTILE + i];
    __syncthreads();

    int* barS = &d_bar[(d * 8 + slot) * 32];
    int* barP = barS - 32;

    // credit for skipped leading diagonals (t < 4*slot): 8 per diag per CTA
    if (tid == 0 && slot > 0) bar_add(barS, 32 * slot);

    const int warp  = tid >> 5;
    const int lane  = tid & 31;
    const int wm    = warp & 3;
    const int wn    = warp >> 2;
    const int lane7 = lane & 7;
    const int lb8   = (lane >> 3) & 1;
    const int lb16  = lane >> 4;
    const int g     = lane >> 2;
    const int tq    = lane & 3;

    // bias registers (channel = lane, fixed over whole t-loop)
    const float bI = bsm[lane];
    const float bF = bsm[32 + lane];
    const float bG = bsm[64 + lane];
    const float bO = bsm[96 + lane];
    const float bL = bsm[128 + lane];

    const uint32_t aAddr0 =
        smem_u32(&As[(wm * 32 + lane7 + lb8 * 8) * AKH + lb16 * 8]);
    const uint32_t aAddr1 = aAddr0 + 16 * AKH * 2;
    uint32_t bAddr[5];
#pragma unroll
    for (int n2 = 0; n2 < 5; n2++)
        bAddr[n2] = smem_u32(
            &Bs[(wn * 80 + n2 * 16 + lb16 * 8 + lane7) * AKH + lb8 * 8]);

    // A-stage phase-A constants
    const int clA   = warp >> 1;
    const int bA0   = (warp & 1) * 16;
    const int selLf = (lane >= 16);
    const int koffA = (lane * 8) & 127;
    const int yA    = slot * 4 + clA;      // absolute row, constant

    // phase-B constants
    const int bB  = tid >> 3;
    const int q8B = tid & 7;

    const int t0 = 4 * slot;
    const int t1 = (4 * slot + 130 < NDIAG - 1) ? (4 * slot + 130) : (NDIAG - 1);

    for (int t = t0; t <= t1; t++) {
        // ===== hoisted phase-B x loads (static data, before flag wait) =====
        uint4 xv[4];
#pragma unroll
        for (int i = 0; i < 4; i++) {
            int y  = slot * 4 + i;
            int x  = t - y;
            xv[i] = make_uint4(0u, 0u, 0u, 0u);
            if (x >= 0 && x < WW) {
                int fy = (d & 2) ? (HH - 1 - y) : y;
                int fx = (d & 1) ? (WW - 1 - x) : x;
                xv[i] = __ldcg((const uint4*)&d_xT16[fy][fx][bB][q8B * 8]);
            }
        }

        // ---- wait: own slot peers + slot-1 done through diag t-1 ----
        if (tid == 0) {
            const int tgt = 32 * t;
            while (bar_ld(barS) < tgt) { }
            if (slot > 0) while (bar_ld(barP) < tgt) { }
        }
        __syncthreads();

        // ===== A-stage phase A: recurrent K (h_up | h_lf) =====
        {
            int x     = t - yA;
            bool valid = (x >= 0) && (x < WW);
            bool up_ok = valid && (yA > 0);
            bool lf_ok = valid && (x > 0);
            int yu = up_ok ? yA - 1 : 0;
            int xl = lf_ok ? x - 1 : 0;
            int xc = valid ? x : 0;
            const __half* pUp = &d_h16[d][yu][xc][0][0];
            const __half* pLf = &d_h16[d][yA][xl][0][0];
            const __half* pSel = selLf ? pLf : pUp;
            const bool pok = selLf ? lf_ok : up_ok;
#pragma unroll
            for (int i = 0; i < 16; i++) {
                int r = warp * 16 + i;
                uint4 v = make_uint4(0u, 0u, 0u, 0u);
                if (pok) v = __ldcg((const uint4*)(pSel + (bA0 + i) * 128 + koffA));
                *(uint4*)&As[r * AKH + lane * 8] = v;
            }
        }
        // ===== A-stage phase B: store hoisted x regs =====
#pragma unroll
        for (int i = 0; i < 4; i++)
            *(uint4*)&As[(i * 32 + bB) * AKH + 256 + q8B * 8] = xv[i];
        __syncthreads();

        // ===== MMA mainloop: software-pipelined (double-buffered frags) =====
        float acc[2][10][4];
#pragma unroll
        for (int mi = 0; mi < 2; mi++)
#pragma unroll
            for (int ni = 0; ni < 10; ni++)
#pragma unroll
                for (int e = 0; e < 4; e++) acc[mi][ni][e] = 0.0f;

        uint32_t afA[2][4], afB[2][4], bfr[2][20];
        ldsm_x4(afA[0][0], afA[0][1], afA[0][2], afA[0][3], aAddr0);
        ldsm_x4(afB[0][0], afB[0][1], afB[0][2], afB[0][3], aAddr1);
#pragma unroll
        for (int n2 = 0; n2 < 5; n2++)
            ldsm_x4(bfr[0][n2*4], bfr[0][n2*4+1], bfr[0][n2*4+2], bfr[0][n2*4+3],
                    bAddr[n2]);

#pragma unroll
        for (int ks = 0; ks < 20; ks++) {
            const int cur = ks & 1;
            const int nxt = cur ^ 1;
            if (ks < 19) {   // prefetch next k-step while MMAs of cur issue
                const uint32_t kb = (ks + 1) * 32;
                ldsm_x4(afA[nxt][0], afA[nxt][1], afA[nxt][2], afA[nxt][3],
                        aAddr0 + kb);
                ldsm_x4(afB[nxt][0], afB[nxt][1], afB[nxt][2], afB[nxt][3],
                        aAddr1 + kb);
#pragma unroll
                for (int n2 = 0; n2 < 5; n2++)
                    ldsm_x4(bfr[nxt][n2*4], bfr[nxt][n2*4+1],
                            bfr[nxt][n2*4+2], bfr[nxt][n2*4+3],
                            bAddr[n2] + kb);
            }
#pragma unroll
            for (int n2 = 0; n2 < 5; n2++) {
                MMA_16816(acc[0][2*n2],   afA[cur][0], afA[cur][1], afA[cur][2],
                          afA[cur][3], bfr[cur][n2*4],   bfr[cur][n2*4+1]);
                MMA_16816(acc[0][2*n2+1], afA[cur][0], afA[cur][1], afA[cur][2],
                          afA[cur][3], bfr[cur][n2*4+2], bfr[cur][n2*4+3]);
                MMA_16816(acc[1][2*n2],   afB[cur][0], afB[cur][1], afB[cur][2],
                          afB[cur][3], bfr[cur][n2*4],   bfr[cur][n2*4+1]);
                MMA_16816(acc[1][2*n2+1], afB[cur][0], afB[cur][1], afB[cur][2],
                          afB[cur][3], bfr[cur][n2*4+2], bfr[cur][n2*4+3]);
            }
        }
        __syncthreads();   // done reading As before overwriting with Csm

        // ===== spill gates to smem =====
#pragma unroll
        for (int mi = 0; mi < 2; mi++) {
#pragma unroll
            for (int ni = 0; ni < 10; ni++) {
                int row = wm * 32 + mi * 16 + g;
                int col = wn * 80 + ni * 8 + tq * 2;
                *(float2*)&Csm[row * CPAD + col] =
                    make_float2(acc[mi][ni][0], acc[mi][ni][1]);
                *(float2*)&Csm[(row + 8) * CPAD + col] =
                    make_float2(acc[mi][ni][2], acc[mi][ni][3]);
            }
        }
        __syncthreads();

        // ===== LSTM epilogue: c-state from smem ring =====
        const float* csmPR = csm + ((t & 1) ^ 1) * (128 * 32);
        float*       csmPW = csm + (t & 1) * (128 * 32);
#pragma unroll
        for (int i = 0; i < 16; i++) {
            int r  = i * 8 + warp;
            int j  = lane;
            int cl = r >> 5, b = r & 31;
            int y  = slot * 4 + cl;
            int x  = t - y;
            if (x >= 0 && x < WW) {
                const float* cr = &Csm[r * CPAD];
                float gi = cr[j]       + bI;
                float gf = cr[32 + j]  + bF;
                float gg = cr[64 + j]  + bG;
                float go = cr[96 + j]  + bO;
                float gl = cr[128 + j] + bL;
                float iv = sig_a(gi);
                float fv = sig_f(gf);      // exact: multiplies large c_prev
                float gv = tanh_a(gg);
                float ov = sig_a(go);
                float lv = sig_a(gl);
                int oc = cb * 32 + j;
                float clf = (x > 0) ? csmPR[r * 32 + j] : 0.0f;
                float cup;
                if (cl > 0)       cup = csmPR[(r - 32) * 32 + j];
                else if (y > 0)   cup = __ldcg(&d_c32[d][y - 1][x][b][oc]);
                else              cup = 0.0f;
                float cn = fv * (lv * cup + (1.0f - lv) * clf) + iv * gv;
                float hn = ov * tanh_a(cn);
                csmPW[r * 32 + j] = cn;
                if (cl == 3) __stcg(&d_c32[d][y][x][b][oc], cn);   // boundary publish
                unsigned short hraw = __half_as_ushort(__float2half(hn));
                asm volatile("st.global.cg.u16 [%0], %1;"
                             :: "l"(&d_h16[d][y][x][b][oc]), "h"(hraw) : "memory");
            }
        }

        // ---- per-warp release: warp stores -> warp fence -> lane0 release ----
        __syncwarp();
        if (lane == 0) bar_add(barS, 1);
        // (no trailing CTA sync: top-of-loop __syncthreads rendezvouses all
        //  warps before As/Csm are overwritten next diagonal)
    }

    // credit for skipped trailing diagonals
    if (tid == 0) {
        int tail = (NDIAG - 1) - t1;
        if (tail > 0) bar_add(barS, 8 * tail);
    }
}

// ---------------------------------------------------------------------------
// final transpose: h16[d][y][xw][b][oc] -> out[b][d][oc][y][xw]
// ---------------------------------------------------------------------------
__global__ void __launch_bounds__(256) finalize_kernel(float* __restrict__ out) {
    int bid = blockIdx.x;
    int occ = bid & 3;
    int b   = (bid >> 2) & 31;
    int y   = (bid >> 7) & 31;
    int d   = bid >> 12;

    __shared__ float sm[128][33];

    for (int i = threadIdx.x; i < 128 * 32; i += 256) {
        int xw = i >> 5;
        int j  = i & 31;
        sm[xw][j] = __half2float(d_h16[d][y][xw][b][occ * 32 + j]);
    }
    __syncthreads();
    for (int i = threadIdx.x; i < 32 * 128; i += 256) {
        int j  = i >> 7;
        int xw = i & 127;
        int oc = occ * 32 + j;
        out[(((size_t)(b * 4 + d) * OCC + oc) * HH + y) * WW + xw] = sm[xw][j];
    }
}

// ---------------------------------------------------------------------------
// launch
// ---------------------------------------------------------------------------
extern "C" void kernel_launch(void* const* d_in, const int* in_sizes, int n_in,
                              void* d_out, int out_size) {
    const float* x  = (const float*)d_in[0];
    const float* w0 = (const float*)d_in[1];
    const float* u0 = (const float*)d_in[2];
    const float* u1 = (const float*)d_in[3];
    const float* bb = (const float*)d_in[4];
    float* out = (float*)d_out;
    (void)in_sizes; (void)n_in; (void)out_size;

    cudaFuncSetAttribute(persist_kernel,
                         cudaFuncAttributeMaxDynamicSharedMemorySize, SMEM_BYTES);

    prep_x<<<(HH * WW * BQ * CINC + 255) / 256, 256>>>(x);
    prep_w<<<(NDIR * G5 * KKK + 255) / 256, 256>>>(w0, u0, u1);
    prep_b<<<(NDIR * G5 + 255) / 256, 256>>>(bb);

    persist_kernel<<<128, 256, SMEM_BYTES>>>();

    finalize_kernel<<<NDIR * HH * BQ * 4, 256>>>(out);
}